// round 3
// baseline (speedup 1.0000x reference)
#include <cuda_runtime.h>
#include <cstdint>

// Bayer mosaic channel select:
//   out[b,i,j] = img[b, c, i, j]
//   c = 1 if (i+j) even; else 2 if i even; else 0
// Row-parity view:
//   i even: j even -> ch1, j odd -> ch2
//   i odd : j even -> ch0, j odd -> ch1
// R1 structure (one float4 per plane per thread, fully coalesced, 32768 CTAs)
// + streaming hint on loads only (zero reuse; 256 MB read streamed once).

static constexpr int B = 8;
static constexpr int C = 3;
static constexpr int H = 2048;
static constexpr int W = 2048;

__global__ __launch_bounds__(256)
void bayer_kernel(const float* __restrict__ img, float* __restrict__ out) {
    const int W4 = W / 4;                       // 512 float4 per row
    int64_t gid = (int64_t)blockIdx.x * blockDim.x + threadIdx.x;
    int j4 = (int)(gid % W4);
    int64_t bi = gid / W4;                      // b*H + i
    int i = (int)(bi % H);
    int b = (int)(bi / H);

    // Channels for this row: cA serves even j, cB serves odd j
    int cA, cB;
    if ((i & 1) == 0) { cA = 1; cB = 2; }
    else              { cA = 0; cB = 1; }

    const int64_t plane = (int64_t)H * W;
    const int64_t row_base = (int64_t)b * C * plane + (int64_t)i * W + (int64_t)j4 * 4;

    const float4 a  = __ldcs(reinterpret_cast<const float4*>(img + row_base + (int64_t)cA * plane));
    const float4 bv = __ldcs(reinterpret_cast<const float4*>(img + row_base + (int64_t)cB * plane));

    float4 o;
    o.x = a.x;   // even j
    o.y = bv.y;  // odd j
    o.z = a.z;   // even j
    o.w = bv.w;  // odd j

    const int64_t out_idx = ((int64_t)b * H + i) * W + (int64_t)j4 * 4;
    *reinterpret_cast<float4*>(out + out_idx) = o;
}

extern "C" void kernel_launch(void* const* d_in, const int* in_sizes, int n_in,
                              void* d_out, int out_size) {
    const float* img = (const float*)d_in[0];
    float* out = (float*)d_out;

    const int64_t total4 = (int64_t)B * H * (W / 4);   // 8,388,608 threads
    const int threads = 256;
    const int blocks = (int)((total4 + threads - 1) / threads);  // 32768
    bayer_kernel<<<blocks, threads>>>(img, out);
}

// round 4
// speedup vs baseline: 1.0274x; 1.0274x over previous
#include <cuda_runtime.h>
#include <cstdint>

// Bayer mosaic channel select:
//   out[b,i,j] = img[b, c, i, j]
//   c = 1 if (i+j) even; else 2 if i even; else 0
// Row-parity view:
//   i even: j even -> ch1, j odd -> ch2
//   i odd : j even -> ch0, j odd -> ch1
// R1 memory pattern (one plain LDG.128 per plane per thread, plain STG.128),
// with a 3D grid so indexing is pure shift/add (no 64-bit div/mod):
//   blockIdx.x in [0,2)   : half-row segment (256 float4 each)
//   blockIdx.y in [0,2048): row i
//   blockIdx.z in [0,8)   : batch b

static constexpr int C = 3;
static constexpr int H = 2048;
static constexpr int W = 2048;

__global__ __launch_bounds__(256)
void bayer_kernel(const float* __restrict__ img, float* __restrict__ out) {
    const int j4 = blockIdx.x * 256 + threadIdx.x;   // float4 index within row
    const int i  = blockIdx.y;
    const int b  = blockIdx.z;

    // Channels for this row: cA serves even j, cB serves odd j
    int cA, cB;
    if ((i & 1) == 0) { cA = 1; cB = 2; }
    else              { cA = 0; cB = 1; }

    const int64_t plane = (int64_t)H * W;
    const int64_t row_base = (int64_t)b * C * plane + (int64_t)i * W + (int64_t)j4 * 4;

    const float4 a  = *reinterpret_cast<const float4*>(img + row_base + (int64_t)cA * plane);
    const float4 bv = *reinterpret_cast<const float4*>(img + row_base + (int64_t)cB * plane);

    float4 o;
    o.x = a.x;   // even j
    o.y = bv.y;  // odd j
    o.z = a.z;   // even j
    o.w = bv.w;  // odd j

    const int64_t out_idx = ((int64_t)b * H + i) * W + (int64_t)j4 * 4;
    *reinterpret_cast<float4*>(out + out_idx) = o;
}

extern "C" void kernel_launch(void* const* d_in, const int* in_sizes, int n_in,
                              void* d_out, int out_size) {
    const float* img = (const float*)d_in[0];
    float* out = (float*)d_out;

    dim3 grid(W / 4 / 256, H, 8);   // (2, 2048, 8) = 32768 CTAs
    bayer_kernel<<<grid, 256>>>(img, out);
}